// round 1
// baseline (speedup 1.0000x reference)
#include <cuda_runtime.h>
#include <cstddef>

// Two-layer LSTM recurrence, persistent kernel.
//   Layer1: in=1, hidden=100.  Layer2: in=100 (takes c1!), hidden=1.
//   Observed phase t<T: x = input[t][b].  Future phase: x = c2 (prev step).
//   Output: out[b][t-T] = c2 at each future step.
//
// Per block: 32 batch elements, full weight matrix W_hh1 staged in SMEM.
// Thread (u, b_tile): computes all 4 gates of unit u for 8 batch elems.
// c1 lives in registers of the owning thread; h1/c1 staged in SMEM per step.

#define CELL     100
#define NGATE    400      // 4*CELL
#define NB       32       // batch per block
#define BT       8        // batch per thread
#define THREADS  512
#define WSTRIDE  101      // W row padding (conflict-free lane pattern)
#define HSTRIDE  33       // h/c1 row padding (conflict-free writes)

__device__ __forceinline__ float sigm(float x) {
    return 1.0f / (1.0f + __expf(-x));
}
__device__ __forceinline__ float tanh_f(float x) {
    // tanh(x) = 1 - 2/(exp(2x)+1); correct limits at +-inf with __expf
    float e = __expf(2.0f * x);
    return 1.0f - 2.0f / (e + 1.0f);
}

__global__ void __launch_bounds__(THREADS, 1)
tsrnn_kernel(const float* __restrict__ input,
             const float* __restrict__ W_ih1, const float* __restrict__ W_hh1,
             const float* __restrict__ b_ih1, const float* __restrict__ b_hh1,
             const float* __restrict__ W_ih2, const float* __restrict__ W_hh2,
             const float* __restrict__ b_ih2, const float* __restrict__ b_hh2,
             float* __restrict__ out, int T, int FUT, int Btot)
{
    extern __shared__ float sm[];
    float* Wsh   = sm;                          // [400][WSTRIDE]
    float* h_sh  = Wsh   + NGATE * WSTRIDE;     // [100][HSTRIDE]  h1, layout [u][b]
    float* c1_sh = h_sh  + CELL * HSTRIDE;      // [100][HSTRIDE]  c1, layout [u][b]
    float* w2_sh = c1_sh + CELL * HSTRIDE;      // [4][100]
    float* g2_sh = w2_sh + 4 * CELL;            // [4][32]
    float* c2_sh = g2_sh + 4 * NB;              // [32]

    const int tid    = threadIdx.x;
    const int u      = tid >> 2;                // unit slot (valid if < CELL)
    const int b0     = (tid & 3) * BT;          // first batch elem of this thread
    const int bglob0 = blockIdx.x * NB;
    const bool act   = (u < CELL);

    // ---- stage weights into SMEM ----
    for (int idx = tid; idx < NGATE * CELL; idx += THREADS) {
        int g = idx / CELL, j = idx - g * CELL;
        Wsh[g * WSTRIDE + j] = W_hh1[idx];
    }
    for (int idx = tid; idx < 4 * CELL; idx += THREADS) w2_sh[idx] = W_ih2[idx];
    for (int idx = tid; idx < CELL * HSTRIDE; idx += THREADS) {
        h_sh[idx]  = 0.0f;
        c1_sh[idx] = 0.0f;
    }
    if (tid < NB) c2_sh[tid] = 0.0f;

    // per-thread constants (layer 1)
    float wih[4], bsum[4];
    if (act) {
        #pragma unroll
        for (int k = 0; k < 4; k++) {
            int g = k * CELL + u;
            wih[k]  = W_ih1[g];
            bsum[k] = b_ih1[g] + b_hh1[g];
        }
    }
    // per-thread constants (layer 2, lane threads)
    float whh2[4], b2c[4];
    float h2 = 0.0f, c2 = 0.0f;
    if (tid < NB) {
        #pragma unroll
        for (int k = 0; k < 4; k++) {
            whh2[k] = W_hh2[k];
            b2c[k]  = b_ih2[k] + b_hh2[k];
        }
    }

    // c1 state in registers
    float c1r[BT];
    #pragma unroll
    for (int bb = 0; bb < BT; bb++) c1r[bb] = 0.0f;

    __syncthreads();

    const int TOT = T + FUT;
    for (int t = 0; t < TOT; ++t) {
        float xv[BT];
        float hn[BT];

        if (act) {
            // ---- fetch x (global loads hidden behind the GEMV below) ----
            if (t < T) {
                const float* xp = input + (size_t)t * Btot + bglob0 + b0;
                #pragma unroll
                for (int bb = 0; bb < BT; bb++) xv[bb] = xp[bb];
            } else {
                #pragma unroll
                for (int bb = 0; bb < BT; bb++) xv[bb] = c2_sh[b0 + bb];
            }

            // ---- layer-1 GEMV: gates[4][BT] += W_hh1 rows . h1 ----
            float a0[BT], a1[BT], a2[BT], a3[BT];
            #pragma unroll
            for (int bb = 0; bb < BT; bb++) { a0[bb] = 0.f; a1[bb] = 0.f; a2[bb] = 0.f; a3[bb] = 0.f; }

            const float* w0p = Wsh + (size_t)u * WSTRIDE;              // gate i row
            const float* w1p = w0p + (size_t)CELL * WSTRIDE;           // gate f row
            const float* w2p = w1p + (size_t)CELL * WSTRIDE;           // gate g row
            const float* w3p = w2p + (size_t)CELL * WSTRIDE;           // gate o row
            const float* hp  = h_sh + b0;

            #pragma unroll 4
            for (int j = 0; j < CELL; j++) {
                float w0 = w0p[j], w1 = w1p[j], w2v = w2p[j], w3 = w3p[j];
                const float* hj = hp + j * HSTRIDE;
                #pragma unroll
                for (int bb = 0; bb < BT; bb++) {
                    float hv = hj[bb];
                    a0[bb] = fmaf(w0,  hv, a0[bb]);
                    a1[bb] = fmaf(w1,  hv, a1[bb]);
                    a2[bb] = fmaf(w2v, hv, a2[bb]);
                    a3[bb] = fmaf(w3,  hv, a3[bb]);
                }
            }

            // ---- layer-1 pointwise ----
            #pragma unroll
            for (int bb = 0; bb < BT; bb++) {
                float pi = fmaf(xv[bb], wih[0], a0[bb] + bsum[0]);
                float pf = fmaf(xv[bb], wih[1], a1[bb] + bsum[1]);
                float pg = fmaf(xv[bb], wih[2], a2[bb] + bsum[2]);
                float po = fmaf(xv[bb], wih[3], a3[bb] + bsum[3]);
                float cn = sigm(pf) * c1r[bb] + sigm(pi) * tanh_f(pg);
                c1r[bb] = cn;
                hn[bb]  = sigm(po) * tanh_f(cn);
            }
        }

        __syncthreads();   // S1: everyone done reading h_sh / c2_sh

        if (act) {
            #pragma unroll
            for (int bb = 0; bb < BT; bb++) {
                h_sh [u * HSTRIDE + b0 + bb] = hn[bb];
                c1_sh[u * HSTRIDE + b0 + bb] = c1r[bb];
            }
        }

        __syncthreads();   // S2: h_sh / c1_sh ready

        // ---- layer-2 gate dots: 4 warps, one gate each, lanes = batch ----
        if (tid < 4 * NB) {
            int k = tid >> 5, b = tid & 31;
            const float* wr = w2_sh + k * CELL;
            float d = 0.0f;
            #pragma unroll 4
            for (int uu = 0; uu < CELL; uu++)
                d = fmaf(c1_sh[uu * HSTRIDE + b], wr[uu], d);
            g2_sh[k * NB + b] = d;
        }

        __syncthreads();   // S3: g2_sh ready

        // ---- layer-2 pointwise + output ----
        if (tid < NB) {
            float pi = g2_sh[0 * NB + tid] + h2 * whh2[0] + b2c[0];
            float pf = g2_sh[1 * NB + tid] + h2 * whh2[1] + b2c[1];
            float pg = g2_sh[2 * NB + tid] + h2 * whh2[2] + b2c[2];
            float po = g2_sh[3 * NB + tid] + h2 * whh2[3] + b2c[3];
            float cn = sigm(pf) * c2 + sigm(pi) * tanh_f(pg);
            c2 = cn;
            h2 = sigm(po) * tanh_f(cn);
            c2_sh[tid] = cn;
            if (t >= T)
                out[(size_t)(bglob0 + tid) * FUT + (t - T)] = cn;
        }

        __syncthreads();   // S4: c2_sh ready for next step's x
    }
}

extern "C" void kernel_launch(void* const* d_in, const int* in_sizes, int n_in,
                              void* d_out, int out_size)
{
    const float* input = (const float*)d_in[0];
    const float* W_ih1 = (const float*)d_in[1];
    const float* W_hh1 = (const float*)d_in[2];
    const float* b_ih1 = (const float*)d_in[3];
    const float* b_hh1 = (const float*)d_in[4];
    const float* W_ih2 = (const float*)d_in[5];
    const float* W_hh2 = (const float*)d_in[6];
    const float* b_ih2 = (const float*)d_in[7];
    const float* b_hh2 = (const float*)d_in[8];
    float* out = (float*)d_out;

    const int Btot = 4096;                 // batch (fixed by problem)
    const int T    = in_sizes[0] / Btot;   // 512
    const int FUT  = out_size   / Btot;    // 64

    const int smem = (NGATE * WSTRIDE        // W_hh1
                      + 2 * CELL * HSTRIDE   // h_sh + c1_sh
                      + 4 * CELL             // W_ih2
                      + 4 * NB               // g2 staging
                      + NB)                  // c2
                     * (int)sizeof(float);   // = 190,240 B

    cudaFuncSetAttribute(tsrnn_kernel,
                         cudaFuncAttributeMaxDynamicSharedMemorySize, smem);

    tsrnn_kernel<<<Btot / NB, THREADS, smem>>>(
        input, W_ih1, W_hh1, b_ih1, b_hh1,
        W_ih2, W_hh2, b_ih2, b_hh2,
        out, T, FUT, Btot);
}

// round 2
// speedup vs baseline: 1.2366x; 1.2366x over previous
#include <cuda_runtime.h>
#include <cstddef>

// Two-layer LSTM recurrence, persistent kernel, f32x2-packed GEMV.
//   Layer1: in=1, hidden=100.  Layer2: in=100 (takes c1), hidden=1.
// 128 blocks x 928 threads. Warps 0-24: layer-1 (unit u = tid>>3, 4 batch
// elems each). Warps 25-28: layer-2 (pipelined one step behind during the
// observed phase; serial during the future phase).

#define CELL     100
#define NB       32       // batch per block
#define BT       4        // batch per layer-1 thread
#define THREADS  928
#define L2BASE   800      // first layer-2 thread

#define FMA2(acc, a, b) asm("fma.rn.f32x2 %0,%1,%2,%0;" : "+l"(acc) : "l"(a), "l"(b))
#define PACK2(dst, s)   asm("mov.b64 %0,{%1,%1};" : "=l"(dst) : "f"(s))
#define UNPK2(lo, hi, s) asm("mov.b64 {%0,%1},%2;" : "=f"(lo), "=f"(hi) : "l"(s))

__device__ __forceinline__ float sigm(float x) {
    return 1.0f / (1.0f + __expf(-x));
}
__device__ __forceinline__ float tanh_f(float x) {
    float e = __expf(2.0f * x);
    return 1.0f - 2.0f / (e + 1.0f);
}

__global__ void __launch_bounds__(THREADS, 1)
tsrnn_kernel(const float* __restrict__ input,
             const float* __restrict__ W_ih1, const float* __restrict__ W_hh1,
             const float* __restrict__ b_ih1, const float* __restrict__ b_hh1,
             const float* __restrict__ W_ih2, const float* __restrict__ W_hh2,
             const float* __restrict__ b_ih2, const float* __restrict__ b_hh2,
             float* __restrict__ out, int T, int FUT, int Btot)
{
    extern __shared__ float sm[];
    float* Wint  = sm;                 // [100][100][4]  (u, j, gate) interleaved
    float* hbuf  = Wint  + 40000;      // [2][100][32]   h1 double buffer
    float* c1buf = hbuf  + 6400;       // [2][100][32]   c1 double buffer
    float* w2_sh = c1buf + 6400;       // [4][100]
    float* g2_sh = w2_sh + 400;        // [4][32]
    float* c2_sh = g2_sh + 128;        // [32]

    const int tid    = threadIdx.x;
    const int bglob0 = blockIdx.x * NB;

    const bool l1 = (tid < L2BASE);
    const bool l2 = (tid >= L2BASE);           // warps 25..28
    const int  u  = tid >> 3;                  // layer-1 unit
    const int  b0 = (tid & 7) * BT;            // layer-1 batch offset

    // ---- stage weights (interleaved by gate) ----
    for (int idx = tid; idx < 4 * CELL * CELL; idx += THREADS) {
        int k = idx & 3, r = idx >> 2;
        int uu = r / CELL, j = r - uu * CELL;
        Wint[idx] = W_hh1[(k * CELL + uu) * CELL + j];
    }
    for (int idx = tid; idx < 4 * CELL; idx += THREADS) w2_sh[idx] = W_ih2[idx];
    for (int idx = tid; idx < 2 * CELL * NB; idx += THREADS) {
        hbuf[idx] = 0.0f; c1buf[idx] = 0.0f;
    }
    if (tid < NB) c2_sh[tid] = 0.0f;

    // layer-1 per-thread constants
    float wih[4], bsum[4];
    if (l1) {
        #pragma unroll
        for (int k = 0; k < 4; k++) {
            int g = k * CELL + u;
            wih[k]  = W_ih1[g];
            bsum[k] = b_ih1[g] + b_hh1[g];
        }
    }
    // layer-2 per-thread constants + state (warp 25 lanes own batch b)
    const int r2 = tid - L2BASE;               // 0..127 for l2 threads
    float whh2[4], b2c[4];
    float h2 = 0.0f, c2 = 0.0f;
    if (l2 && r2 < NB) {
        #pragma unroll
        for (int k = 0; k < 4; k++) {
            whh2[k] = W_hh2[k];
            b2c[k]  = b_ih2[k] + b_hh2[k];
        }
    }

    float c1r[BT];
    #pragma unroll
    for (int bb = 0; bb < BT; bb++) c1r[bb] = 0.0f;

    const float* wp = Wint + u * (4 * CELL);
    const int TOT = T + FUT;

    // ================= layer-1 step (macro-ish lambda) =================
    auto layer1_step = [&](const float4 xq, const float* __restrict__ hold,
                           float* __restrict__ hnew, float* __restrict__ c1new) {
        unsigned long long A00 = 0ull, A01 = 0ull, A10 = 0ull, A11 = 0ull,
                           A20 = 0ull, A21 = 0ull, A30 = 0ull, A31 = 0ull;
        const float* hp = hold + b0;
        #pragma unroll 2
        for (int j = 0; j < CELL; j++) {
            float4 w4 = *(const float4*)(wp + j * 4);
            ulonglong2 hv = *(const ulonglong2*)(hp + j * NB);
            unsigned long long W0, W1, W2, W3;
            PACK2(W0, w4.x); PACK2(W1, w4.y); PACK2(W2, w4.z); PACK2(W3, w4.w);
            FMA2(A00, W0, hv.x); FMA2(A01, W0, hv.y);
            FMA2(A10, W1, hv.x); FMA2(A11, W1, hv.y);
            FMA2(A20, W2, hv.x); FMA2(A21, W2, hv.y);
            FMA2(A30, W3, hv.x); FMA2(A31, W3, hv.y);
        }
        float g0[BT], g1[BT], g2[BT], g3[BT];
        UNPK2(g0[0], g0[1], A00); UNPK2(g0[2], g0[3], A01);
        UNPK2(g1[0], g1[1], A10); UNPK2(g1[2], g1[3], A11);
        UNPK2(g2[0], g2[1], A20); UNPK2(g2[2], g2[3], A21);
        UNPK2(g3[0], g3[1], A30); UNPK2(g3[2], g3[3], A31);

        const float xv[BT] = {xq.x, xq.y, xq.z, xq.w};
        float hn[BT], cn[BT];
        #pragma unroll
        for (int bb = 0; bb < BT; bb++) {
            float pi = fmaf(xv[bb], wih[0], g0[bb] + bsum[0]);
            float pf = fmaf(xv[bb], wih[1], g1[bb] + bsum[1]);
            float pg = fmaf(xv[bb], wih[2], g2[bb] + bsum[2]);
            float po = fmaf(xv[bb], wih[3], g3[bb] + bsum[3]);
            float c  = sigm(pf) * c1r[bb] + sigm(pi) * tanh_f(pg);
            c1r[bb] = c;
            cn[bb]  = c;
            hn[bb]  = sigm(po) * tanh_f(c);
        }
        *(float4*)(hnew  + u * NB + b0) = make_float4(hn[0], hn[1], hn[2], hn[3]);
        *(float4*)(c1new + u * NB + b0) = make_float4(cn[0], cn[1], cn[2], cn[3]);
    };

    // ================= layer-2 step =================
    auto layer2_step = [&](const float* __restrict__ c1p, int tt, bool wr_out) {
        int k = r2 >> 5, b = r2 & 31;
        const float* wr = w2_sh + k * CELL;
        const float* cp = c1p + b;
        float d0 = 0.f, d1 = 0.f, d2 = 0.f, d3 = 0.f;
        #pragma unroll 5
        for (int uu = 0; uu < CELL; uu += 4) {
            d0 = fmaf(cp[(uu + 0) * NB], wr[uu + 0], d0);
            d1 = fmaf(cp[(uu + 1) * NB], wr[uu + 1], d1);
            d2 = fmaf(cp[(uu + 2) * NB], wr[uu + 2], d2);
            d3 = fmaf(cp[(uu + 3) * NB], wr[uu + 3], d3);
        }
        g2_sh[k * NB + b] = (d0 + d1) + (d2 + d3);
        asm volatile("bar.sync 1, 128;" ::: "memory");
        if (r2 < NB) {
            float pi = fmaf(h2, whh2[0], g2_sh[0 * NB + r2] + b2c[0]);
            float pf = fmaf(h2, whh2[1], g2_sh[1 * NB + r2] + b2c[1]);
            float pg = fmaf(h2, whh2[2], g2_sh[2 * NB + r2] + b2c[2]);
            float po = fmaf(h2, whh2[3], g2_sh[3 * NB + r2] + b2c[3]);
            float c  = sigm(pf) * c2 + sigm(pi) * tanh_f(pg);
            c2 = c;
            h2 = sigm(po) * tanh_f(c);
            c2_sh[r2] = c;
            if (wr_out) out[(size_t)(bglob0 + r2) * FUT + (tt - T)] = c;
        }
    };

    // ================= observed phase (pipelined, 1 sync/step) =========
    for (int t = 0; t < T; ++t) {
        __syncthreads();
        if (l1) {
            float4 xq = *(const float4*)(input + (size_t)t * Btot + bglob0 + b0);
            layer1_step(xq,
                        hbuf  + ((t + 1) & 1) * (CELL * NB),
                        hbuf  + (t & 1) * (CELL * NB),
                        c1buf + (t & 1) * (CELL * NB));
        } else if (t > 0) {
            layer2_step(c1buf + ((t - 1) & 1) * (CELL * NB), t - 1, false);
        }
    }
    // drain: layer-2 for step T-1
    __syncthreads();
    if (l2) layer2_step(c1buf + ((T - 1) & 1) * (CELL * NB), T - 1, false);

    // ================= future phase (serial, 2 syncs/step) =============
    for (int t = T; t < TOT; ++t) {
        __syncthreads();
        if (l1) {
            float4 xq = *(const float4*)(c2_sh + b0);
            layer1_step(xq,
                        hbuf  + ((t + 1) & 1) * (CELL * NB),
                        hbuf  + (t & 1) * (CELL * NB),
                        c1buf + (t & 1) * (CELL * NB));
        }
        __syncthreads();
        if (l2) layer2_step(c1buf + (t & 1) * (CELL * NB), t, true);
    }
}

extern "C" void kernel_launch(void* const* d_in, const int* in_sizes, int n_in,
                              void* d_out, int out_size)
{
    const float* input = (const float*)d_in[0];
    const float* W_ih1 = (const float*)d_in[1];
    const float* W_hh1 = (const float*)d_in[2];
    const float* b_ih1 = (const float*)d_in[3];
    const float* b_hh1 = (const float*)d_in[4];
    const float* W_ih2 = (const float*)d_in[5];
    const float* W_hh2 = (const float*)d_in[6];
    const float* b_ih2 = (const float*)d_in[7];
    const float* b_hh2 = (const float*)d_in[8];
    float* out = (float*)d_out;

    const int Btot = 4096;
    const int T    = in_sizes[0] / Btot;   // 512
    const int FUT  = out_size   / Btot;    // 64

    const int smem = (40000            // Wint
                      + 2 * 6400       // h + c1 double buffers
                      + 400 + 128 + 32)
                     * (int)sizeof(float);  // 213,440 B

    cudaFuncSetAttribute(tsrnn_kernel,
                         cudaFuncAttributeMaxDynamicSharedMemorySize, smem);

    tsrnn_kernel<<<Btot / NB, THREADS, smem>>>(
        input, W_ih1, W_hh1, b_ih1, b_hh1,
        W_ih2, W_hh2, b_ih2, b_hh2,
        out, T, FUT, Btot);
}